// round 4
// baseline (speedup 1.0000x reference)
#include <cuda_runtime.h>
#include <math_constants.h>

// Problem constants (fixed by the dataset)
#define Bb 4
#define Hh 512
#define Ww 512
#define Cc 32
#define HO 256
#define WO 256
#define HP 514                   // padded height (1-pixel halo)
#define WP 514                   // padded width
#define NPAD (Bb*HP*WP)

// Per-pixel slot over the PADDED grid: 0 = empty, else (point_index + 1).
// Zero-initialized at module load; every kernel_launch call restores the
// all-zero state via unscatter_kernel, so no bulk clear is ever needed.
__device__ int g_slot[NPAD];

__global__ void scatter_kernel(const int* __restrict__ coors, int n_pts) {
    int n = blockIdx.x * blockDim.x + threadIdx.x;
    if (n >= n_pts) return;
    int b = coors[n * 3 + 0];
    int y = coors[n * 3 + 1];
    int x = coors[n * 3 + 2];
    g_slot[(b * HP + (y + 1)) * WP + (x + 1)] = n + 1;
}

__global__ void unscatter_kernel(const int* __restrict__ coors, int n_pts) {
    int n = blockIdx.x * blockDim.x + threadIdx.x;
    if (n >= n_pts) return;
    int b = coors[n * 3 + 0];
    int y = coors[n * 3 + 1];
    int x = coors[n * 3 + 2];
    g_slot[(b * HP + (y + 1)) * WP + (x + 1)] = 0;
}

// 8 threads per PAIR of horizontally-adjacent output pixels (4 channels each as
// float4). The two 3x3 windows share a column: 15 slot probes (front-batched,
// MLP=15) and at most 15 feature gathers serve both pixels.
__global__ void __launch_bounds__(256) pool_kernel(const float* __restrict__ feat,
                                                   float* __restrict__ out) {
    int t      = blockIdx.x * blockDim.x + threadIdx.x;
    int pairId = t >> 3;              // which pixel pair (exact grid)
    int lane8  = t & 7;               // channel chunk: 4 floats

    int xp = pairId & (WO / 2 - 1);   // pair x: 0..127
    int yo = (pairId >> 7) & (HO - 1);
    int b  = pairId >> 15;

    // window top-left of left pixel in padded coords: (2*yo, 4*xp)
    const int* __restrict__ sp = g_slot + ((b * HP + 2 * yo) * WP + 4 * xp);

    // 15 independent probes over 3 rows x 5 cols
    int r0c0 = __ldg(sp);              int r0c1 = __ldg(sp + 1);
    int r0c2 = __ldg(sp + 2);          int r0c3 = __ldg(sp + 3);
    int r0c4 = __ldg(sp + 4);
    int r1c0 = __ldg(sp + WP);         int r1c1 = __ldg(sp + WP + 1);
    int r1c2 = __ldg(sp + WP + 2);     int r1c3 = __ldg(sp + WP + 3);
    int r1c4 = __ldg(sp + WP + 4);
    int r2c0 = __ldg(sp + 2 * WP);     int r2c1 = __ldg(sp + 2 * WP + 1);
    int r2c2 = __ldg(sp + 2 * WP + 2); int r2c3 = __ldg(sp + 2 * WP + 3);
    int r2c4 = __ldg(sp + 2 * WP + 4);

    int anyA = r0c0 | r0c1 | r0c2 | r1c0 | r1c1 | r1c2 | r2c0 | r2c1 | r2c2;
    int anyB = r0c2 | r0c3 | r0c4 | r1c2 | r1c3 | r1c4 | r2c2 | r2c3 | r2c4;

    const float4* __restrict__ f4 = reinterpret_cast<const float4*>(feat);
    float4 accA = make_float4(-CUDART_INF_F, -CUDART_INF_F, -CUDART_INF_F, -CUDART_INF_F);
    float4 accB = accA;

    #define MAX4(A, V) { A.x = fmaxf(A.x, V.x); A.y = fmaxf(A.y, V.y); \
                         A.z = fmaxf(A.z, V.z); A.w = fmaxf(A.w, V.w); }
    #define GA(S)  if (S) { float4 v = f4[(size_t)((S) - 1) * 8 + lane8]; MAX4(accA, v) }
    #define GB(S)  if (S) { float4 v = f4[(size_t)((S) - 1) * 8 + lane8]; MAX4(accB, v) }
    #define GAB(S) if (S) { float4 v = f4[(size_t)((S) - 1) * 8 + lane8]; MAX4(accA, v) MAX4(accB, v) }

    GA(r0c0) GA(r0c1) GAB(r0c2) GB(r0c3) GB(r0c4)
    GA(r1c0) GA(r1c1) GAB(r1c2) GB(r1c3) GB(r1c4)
    GA(r2c0) GA(r2c1) GAB(r2c2) GB(r2c3) GB(r2c4)

    #undef GA
    #undef GB
    #undef GAB
    #undef MAX4

    float4 zero = make_float4(0.f, 0.f, 0.f, 0.f);
    float4 oA = anyA ? accA : zero;
    float4 oB = anyB ? accB : zero;

    float4* __restrict__ o4 = reinterpret_cast<float4*>(out);
    size_t obase = (size_t)pairId * 16 + lane8;   // pixel 2*pairId
    o4[obase]     = oA;
    o4[obase + 8] = oB;
}

extern "C" void kernel_launch(void* const* d_in, const int* in_sizes, int n_in,
                              void* d_out, int out_size) {
    const float* feat  = (const float*)d_in[0];
    const int*   coors = (const int*)d_in[1];
    (void)n_in; (void)out_size;

    int n_pts = in_sizes[0] / Cc;   // 300000

    // 1) scatter point indices into the (all-zero) padded slot map
    scatter_kernel<<<(n_pts + 255) / 256, 256>>>(coors, n_pts);

    // 2) pair-wise 3x3/s2 max-pool, gathering features from the input array
    {
        int total = Bb * HO * (WO / 2) * 8;   // 1,048,576 threads
        pool_kernel<<<total / 256, 256>>>(feat, (float*)d_out);
    }

    // 3) restore the all-zero slot map for the next call / graph replay
    unscatter_kernel<<<(n_pts + 255) / 256, 256>>>(coors, n_pts);
}